// round 7
// baseline (speedup 1.0000x reference)
#include <cuda_runtime.h>

#define DB 2     // batch
#define DL 64    // L
#define DT 32    // T
#define DD 256   // D
#define G  8     // j-columns per tile
#define NTILES (DB * DL * DL / G)   // 1024

// Scratch (device globals: no allocation allowed)
__device__ float g_Qk[DB * DL * DD];      // per (b,i): ((q@Wq^T+bq)/16)@Wk
__device__ float g_WcombT[DD * DD];       // WcombT[d,f] = sum_e Wv[e,d]*Wf[f,e]
__device__ float g_bcomb[DD];             // bcomb[f] = sum_e Wf[f,e]*bv[e] + bf[f]
__device__ int   g_ticket;                // dynamic tile ticket

// ---------------------------------------------------------------------------
// Single prologue kernel, block = (32,32) = 1024 threads.
// ---------------------------------------------------------------------------
__global__ void prologue_kernel(const float* __restrict__ query,
                                const float* __restrict__ Wq,
                                const float* __restrict__ bq,
                                const float* __restrict__ Wk,
                                const float* __restrict__ Wv,
                                const float* __restrict__ bv,
                                const float* __restrict__ Wf,
                                const float* __restrict__ bf) {
    const int tx = threadIdx.x, ty = threadIdx.y;
    const int tid = ty * 32 + tx;
    const int blk = blockIdx.x;

    if (blk < 64) {
        __shared__ float Av[2][32][33];   // Av[buf][k][m] = Wv[e0+k, d0+m]
        __shared__ float Bf[2][32][33];   // Bf[buf][m][k] = Wf[f0+m, e0+k]
        const int f0 = (blk & 7) * 32;
        const int d0 = (blk >> 3) * 32;

        Av[0][ty][tx] = Wv[(size_t)ty * DD + d0 + tx];
        Bf[0][ty][tx] = Wf[(size_t)(f0 + ty) * DD + tx];
        __syncthreads();

        float acc = 0.f;
#pragma unroll
        for (int s = 0; s < 8; s++) {
            const int cur = s & 1;
            if (s < 7) {
                const int e0 = (s + 1) * 32;
                Av[cur ^ 1][ty][tx] = Wv[(size_t)(e0 + ty) * DD + d0 + tx];
                Bf[cur ^ 1][ty][tx] = Wf[(size_t)(f0 + ty) * DD + e0 + tx];
            }
#pragma unroll
            for (int k = 0; k < 32; k++) acc += Av[cur][k][ty] * Bf[cur][tx][k];
            __syncthreads();
        }
        g_WcombT[(size_t)(d0 + ty) * DD + f0 + tx] = acc;

    } else if (blk < 192) {
        const int bi = blk - 64;
        __shared__ float q[DD];
        __shared__ float Qs[DD];
        __shared__ float part[4][DD];

        if (tid < DD) q[tid] = query[bi * DD + tid];
        __syncthreads();

#pragma unroll
        for (int i = 0; i < 8; i++) {
            const int e = ty * 8 + i;
            const float* wq = Wq + (size_t)e * DD;
            float p = 0.f;
#pragma unroll
            for (int c = 0; c < 8; c++) p += q[tx + 32 * c] * wq[tx + 32 * c];
#pragma unroll
            for (int off = 16; off; off >>= 1)
                p += __shfl_xor_sync(0xffffffffu, p, off);
            if (tx == 0) Qs[e] = (p + bq[e]) * 0.0625f;
        }
        __syncthreads();

        const int quarter = ty >> 3;
        const int d = tx + (ty & 7) * 32;
        const int e0 = quarter * 64;
        float acc = 0.f;
#pragma unroll 8
        for (int e = 0; e < 64; e++)
            acc += Qs[e0 + e] * Wk[(size_t)(e0 + e) * DD + d];
        part[quarter][d] = acc;
        __syncthreads();
        if (tid < DD)
            g_Qk[bi * DD + tid] = part[0][tid] + part[1][tid] + part[2][tid] + part[3][tid];

    } else {
        if (tid == 0) g_ticket = 0;
        __shared__ float bvs[DD];
        if (tid < DD) bvs[tid] = bv[tid];
        __syncthreads();
#pragma unroll
        for (int i = 0; i < 8; i++) {
            const int f = ty * 8 + i;
            const float* wf = Wf + (size_t)f * DD;
            float p = 0.f;
#pragma unroll
            for (int c = 0; c < 8; c++) p += bvs[tx + 32 * c] * wf[tx + 32 * c];
#pragma unroll
            for (int off = 16; off; off >>= 1)
                p += __shfl_xor_sync(0xffffffffu, p, off);
            if (tx == 0) g_bcomb[f] = p + bf[f];
        }
    }
}

// ---------------------------------------------------------------------------
// Phase-A helpers: eager binary-tree score fold (bit-reversed t order).
// ---------------------------------------------------------------------------
__device__ __forceinline__ float fold2(float x, float y, int o, int lane) {
    const bool hi = (lane & o) != 0;
    const float send = hi ? x : y;
    const float recv = __shfl_xor_sync(0xffffffffu, send, o);
    return (hi ? y : x) + recv;
}

__device__ __forceinline__ float score_pair(const float4* __restrict__ kp,
                                            int lane,
                                            const float4 qk0, const float4 qk1,
                                            int t) {
    const float4 a0 = __ldcs(kp + t * 64 + lane);
    const float4 a1 = __ldcs(kp + t * 64 + 32 + lane);
    const float4 b0 = __ldcs(kp + (t + 16) * 64 + lane);
    const float4 b1 = __ldcs(kp + (t + 16) * 64 + 32 + lane);
    const float sa = a0.x * qk0.x + a0.y * qk0.y + a0.z * qk0.z + a0.w * qk0.w
                   + a1.x * qk1.x + a1.y * qk1.y + a1.z * qk1.z + a1.w * qk1.w;
    const float sb = b0.x * qk0.x + b0.y * qk0.y + b0.z * qk0.z + b0.w * qk0.w
                   + b1.x * qk1.x + b1.y * qk1.y + b1.z * qk1.z + b1.w * qk1.w;
    return fold2(sa, sb, 16, lane);
}

// ---------------------------------------------------------------------------
// Main kernel: persistent blocks + ticket; 48-reg cap -> 5 blocks/SM resident
// (40 warps/SM). grid = 740, block = 256 (warp w owns j = j0 + w per tile).
// ---------------------------------------------------------------------------
__global__ __launch_bounds__(256, 5)
void attn_main_kernel(const float4* __restrict__ key4,
                      const float4* __restrict__ value4,
                      float* __restrict__ out) {
    const int tid  = threadIdx.x;
    const int w    = tid >> 5;
    const int lane = tid & 31;

    __shared__ int    s_tile;
    __shared__ float4 vbar_sh[G * 64];         // [jj][64 float4]

    for (;;) {
        __syncthreads();                        // vbar_sh reuse + s_tile safety
        if (tid == 0) s_tile = atomicAdd(&g_ticket, 1);
        __syncthreads();
        const int tile = s_tile;
        if (tile >= NTILES) return;

        const int bi = tile >> 3;               // (b*L + i), 0..127
        const int j0 = (tile & 7) * G;
        const int j  = j0 + w;

        const float4* qk4 = reinterpret_cast<const float4*>(g_Qk) + bi * 64;
        const float4 qk0 = qk4[lane];
        const float4 qk1 = qk4[32 + lane];

        const size_t base = (size_t)(bi * DL + j) * (DT * 64);   // float4 units
        const float4* kp = key4 + base;
        const float4* vp = value4 + base;

        // ---- Phase A: eager tree fold, <=4 live score regs ----
        float h0, h1;
        {
            float m08 = fold2(score_pair(kp, lane, qk0, qk1, 0),
                              score_pair(kp, lane, qk0, qk1, 8), 8, lane);
            float m4  = fold2(score_pair(kp, lane, qk0, qk1, 4),
                              score_pair(kp, lane, qk0, qk1, 12), 8, lane);
            float q0  = fold2(m08, m4, 4, lane);
            float m2  = fold2(score_pair(kp, lane, qk0, qk1, 2),
                              score_pair(kp, lane, qk0, qk1, 10), 8, lane);
            float m6  = fold2(score_pair(kp, lane, qk0, qk1, 6),
                              score_pair(kp, lane, qk0, qk1, 14), 8, lane);
            float q1  = fold2(m2, m6, 4, lane);
            h0 = fold2(q0, q1, 2, lane);        // all even t
        }
        {
            float m1  = fold2(score_pair(kp, lane, qk0, qk1, 1),
                              score_pair(kp, lane, qk0, qk1, 9), 8, lane);
            float m5  = fold2(score_pair(kp, lane, qk0, qk1, 5),
                              score_pair(kp, lane, qk0, qk1, 13), 8, lane);
            float q2  = fold2(m1, m5, 4, lane);
            float m3  = fold2(score_pair(kp, lane, qk0, qk1, 3),
                              score_pair(kp, lane, qk0, qk1, 11), 8, lane);
            float m7  = fold2(score_pair(kp, lane, qk0, qk1, 7),
                              score_pair(kp, lane, qk0, qk1, 15), 8, lane);
            float q3  = fold2(m3, m7, 4, lane);
            h1 = fold2(q2, q3, 2, lane);        // all odd t
        }
        const float myscore = fold2(h0, h1, 1, lane);   // lane l = score[t=l]

        // ---- warp-local softmax over T=32 ----
        float m = myscore;
#pragma unroll
        for (int off = 16; off; off >>= 1)
            m = fmaxf(m, __shfl_xor_sync(0xffffffffu, m, off));
        const float ex = __expf(myscore - m);
        float ssum = ex;
#pragma unroll
        for (int off = 16; off; off >>= 1)
            ssum += __shfl_xor_sync(0xffffffffu, ssum, off);
        const float a = ex / ssum;              // attn[t = lane]

        // ---- Phase B: vbar[d] = sum_t attn[t] * value[t,d] ----
        float4 acc0 = make_float4(0.f, 0.f, 0.f, 0.f);
        float4 acc1 = make_float4(0.f, 0.f, 0.f, 0.f);
#pragma unroll
        for (int t = 0; t < DT; t++) {
            const float at = __shfl_sync(0xffffffffu, a, t);
            const float4 v0 = __ldcs(vp + t * 64 + lane);
            const float4 v1 = __ldcs(vp + t * 64 + 32 + lane);
            acc0.x += at * v0.x; acc0.y += at * v0.y;
            acc0.z += at * v0.z; acc0.w += at * v0.w;
            acc1.x += at * v1.x; acc1.y += at * v1.y;
            acc1.z += at * v1.z; acc1.w += at * v1.w;
        }
        vbar_sh[w * 64 + lane]      = acc0;
        vbar_sh[w * 64 + 32 + lane] = acc1;
        __syncthreads();

        // ---- Phase C: out[j0+jj, f] = bcomb[f] + sum_d vbar[jj][d]*WcombT[d,f] ----
        const int f = tid;
        float acc[G];
        const float bc = __ldg(&g_bcomb[f]);
#pragma unroll
        for (int jj = 0; jj < G; jj++) acc[jj] = bc;

#pragma unroll 4
        for (int d4 = 0; d4 < 64; d4++) {
            const float* wt = &g_WcombT[(size_t)(d4 * 4) * DD + f];  // coalesced over f
            const float w0 = __ldg(wt);
            const float w1 = __ldg(wt + DD);
            const float w2 = __ldg(wt + 2 * DD);
            const float w3 = __ldg(wt + 3 * DD);
#pragma unroll
            for (int jj = 0; jj < G; jj++) {
                const float4 v = vbar_sh[jj * 64 + d4];
                acc[jj] += v.x * w0 + v.y * w1 + v.z * w2 + v.w * w3;
            }
        }

        const size_t obase = (size_t)(bi * DL + j0) * DD + f;
#pragma unroll
        for (int jj = 0; jj < G; jj++)
            __stcs(&out[obase + (size_t)jj * DD], acc[jj]);
    }
}

// ---------------------------------------------------------------------------
// Launch. Input order: key, value, query, Wk, bk, Wv, bv, Wq, bq, Wf, bf
// ---------------------------------------------------------------------------
extern "C" void kernel_launch(void* const* d_in, const int* in_sizes, int n_in,
                              void* d_out, int out_size) {
    const float* key   = (const float*)d_in[0];
    const float* value = (const float*)d_in[1];
    const float* query = (const float*)d_in[2];
    const float* Wk    = (const float*)d_in[3];
    // bk (d_in[4]) cancels under softmax — unused.
    const float* Wv    = (const float*)d_in[5];
    const float* bv    = (const float*)d_in[6];
    const float* Wq    = (const float*)d_in[7];
    const float* bq    = (const float*)d_in[8];
    const float* Wf    = (const float*)d_in[9];
    const float* bf    = (const float*)d_in[10];
    float* out = (float*)d_out;

    prologue_kernel<<<193, dim3(32, 32)>>>(query, Wq, bq, Wk, Wv, bv, Wf, bf);

    attn_main_kernel<<<740, 256>>>(
        reinterpret_cast<const float4*>(key),
        reinterpret_cast<const float4*>(value),
        out);
}